// round 2
// baseline (speedup 1.0000x reference)
#include <cuda_runtime.h>

#define NEG_SLOPE 0.2f
#define MAXN 100000
#define MAXE 3200000

// ---- scratch (static __device__ arrays; no allocation anywhere) ----
__device__ __align__(16) float g_h0 [MAXN];
__device__ __align__(16) float g_p1 [MAXN * 16];   // layer1 per (node,head): {S, den} pairs
__device__ __align__(16) float g_h2 [MAXN * 16];
__device__ __align__(16) float g_als2[MAXN * 4];
__device__ __align__(16) float g_ald2[MAXN * 4];
__device__ __align__(16) float g_num2[MAXN * 16];
__device__ __align__(16) float g_den2[MAXN * 4];
__device__ __align__(16) float g_h3 [MAXN * 8];
__device__ __align__(16) float g_als3[MAXN * 2];
__device__ __align__(16) float g_ald3[MAXN * 2];
__device__ __align__(16) float g_num3[MAXN * 8];
__device__ __align__(16) float g_den3[MAXN * 2];
__device__ __align__(16) float g_x6 [MAXN * 8];
__device__ __align__(16) float g_ka [16];          // layer1 head consts: kas[8], kad[8]

// ---- CSR scratch ----
// counts/rows: [0..N) = in-degree (by dst), [N..2N) = out-degree (by src)
__device__ int g_cnt[2 * MAXN];
__device__ int g_rs [2 * MAXN];
__device__ int g_cur[2 * MAXN];
__device__ int g_adj[2 * MAXE];    // in-adj (src lists) + out-adj (dst lists), combined index space
__device__ int g_bsum[256];

__device__ __forceinline__ float lrelu(float x) { return x > 0.f ? x : NEG_SLOPE * x; }

__device__ __forceinline__ float wred(float v) {
    #pragma unroll
    for (int o = 16; o > 0; o >>= 1) v += __shfl_xor_sync(0xffffffffu, v, o);
    return v;
}

// ---------- zero counters ----------
__global__ void k_zero(int L) {
    int i = blockIdx.x * blockDim.x + threadIdx.x;
    if (i < L) g_cnt[i] = 0;
}

// ---------- K0: h0 = relu(x1@lin1w^T + b); layer1 self-term init; ka consts ----------
__global__ void k_node0(const float* __restrict__ x1,
                        const float* __restrict__ lin1w, const float* __restrict__ lin1b,
                        const float* __restrict__ W1,
                        const float* __restrict__ as1, const float* __restrict__ ad1,
                        int N)
{
    int n = blockIdx.x * blockDim.x + threadIdx.x;
    if (n >= N) return;
    if (n == 0) {
        #pragma unroll
        for (int h = 0; h < 8; h++) {
            float kas = 0.f, kad = 0.f;
            #pragma unroll
            for (int c = 0; c < 4; c++) {
                float w = W1[h * 4 + c];
                kas = fmaf(w, as1[h * 4 + c], kas);
                kad = fmaf(w, ad1[h * 4 + c], kad);
            }
            g_ka[h] = kas; g_ka[8 + h] = kad;
        }
    }
    float h0 = __ldg(&lin1b[0]);
    #pragma unroll
    for (int i = 0; i < 7; i++) h0 = fmaf(__ldg(&x1[n * 7 + i]), __ldg(&lin1w[i]), h0);
    h0 = fmaxf(h0, 0.f);
    g_h0[n] = h0;
    #pragma unroll
    for (int h = 0; h < 8; h++) {
        float kas = 0.f, kad = 0.f;
        #pragma unroll
        for (int c = 0; c < 4; c++) {
            float w = __ldg(&W1[h * 4 + c]);
            kas = fmaf(w, __ldg(&as1[h * 4 + c]), kas);
            kad = fmaf(w, __ldg(&ad1[h * 4 + c]), kad);
        }
        float ws = __expf(lrelu(h0 * (kas + kad)));
        g_p1[n * 16 + h * 2]     = ws * h0;  // S (self term)
        g_p1[n * 16 + h * 2 + 1] = ws;       // den (self term)
    }
}

// ---------- CSR build ----------
__global__ void k_hist(const int* __restrict__ ei, int E, int N)
{
    int e = blockIdx.x * blockDim.x + threadIdx.x;
    if (e >= E) return;
    int s = __ldg(&ei[e]);
    int d = __ldg(&ei[E + e]);
    if (s == d) return;
    atomicAdd(&g_cnt[d], 1);        // in-degree of d
    atomicAdd(&g_cnt[N + s], 1);    // out-degree of s
}

__global__ void k_scan1(int L)   // per-block inclusive scan -> exclusive result + block sums
{
    __shared__ int sh[1024];
    int i = blockIdx.x * 1024 + threadIdx.x;
    int v = (i < L) ? g_cnt[i] : 0;
    sh[threadIdx.x] = v;
    #pragma unroll
    for (int off = 1; off < 1024; off <<= 1) {
        __syncthreads();
        int t = (threadIdx.x >= off) ? sh[threadIdx.x - off] : 0;
        __syncthreads();
        sh[threadIdx.x] += t;
    }
    __syncthreads();
    if (i < L) g_rs[i] = sh[threadIdx.x] - v;
    if (threadIdx.x == 1023) g_bsum[blockIdx.x] = sh[1023];
}

__global__ void k_scan2(int nb)  // single block: exclusive scan of block sums
{
    __shared__ int sh[256];
    int v = (threadIdx.x < nb) ? g_bsum[threadIdx.x] : 0;
    sh[threadIdx.x] = v;
    #pragma unroll
    for (int off = 1; off < 256; off <<= 1) {
        __syncthreads();
        int t = (threadIdx.x >= off) ? sh[threadIdx.x - off] : 0;
        __syncthreads();
        sh[threadIdx.x] += t;
    }
    __syncthreads();
    if (threadIdx.x < nb) g_bsum[threadIdx.x] = sh[threadIdx.x] - v;
}

__global__ void k_scan3(int L)
{
    int i = blockIdx.x * 1024 + threadIdx.x;
    if (i < L) {
        int r = g_rs[i] + g_bsum[blockIdx.x];
        g_rs[i]  = r;
        g_cur[i] = r;
    }
}

__global__ void k_scatter(const int* __restrict__ ei, int E, int N)
{
    int e = blockIdx.x * blockDim.x + threadIdx.x;
    if (e >= E) return;
    int s = __ldg(&ei[e]);
    int d = __ldg(&ei[E + e]);
    if (s == d) return;
    int p = atomicAdd(&g_cur[d], 1);     g_adj[p] = s;   // in-adj of d
    int q = atomicAdd(&g_cur[N + s], 1); g_adj[q] = d;   // out-adj of s
}

// ---------- G1: layer1 gather (rank-1), warp per node ----------
__global__ void __launch_bounds__(256) k_gat1(int N)
{
    int warp = (blockIdx.x * blockDim.x + threadIdx.x) >> 5;
    int lane = threadIdx.x & 31;
    if (warp >= N) return;
    int n = warp;
    int start = g_rs[n], end = start + g_cnt[n];
    float h0d = __ldg(&g_h0[n]);
    float kas[8], kad[8];
    #pragma unroll
    for (int h = 0; h < 8; h++) { kas[h] = g_ka[h]; kad[h] = g_ka[8 + h]; }
    float S[8], Wv[8];
    #pragma unroll
    for (int h = 0; h < 8; h++) { S[h] = 0.f; Wv[h] = 0.f; }
    for (int i = start + lane; i < end; i += 32) {
        int s = __ldg(&g_adj[i]);
        float h0s = __ldg(&g_h0[s]);
        #pragma unroll
        for (int h = 0; h < 8; h++) {
            float w = __expf(lrelu(fmaf(kas[h], h0s, kad[h] * h0d)));
            S[h] = fmaf(w, h0s, S[h]);
            Wv[h] += w;
        }
    }
    #pragma unroll
    for (int h = 0; h < 8; h++) { S[h] = wred(S[h]); Wv[h] = wred(Wv[h]); }
    if (lane == 0) {
        #pragma unroll
        for (int h = 0; h < 8; h++) {
            g_p1[n * 16 + h * 2]     += S[h];
            g_p1[n * 16 + h * 2 + 1] += Wv[h];
        }
    }
}

// ---------- K2: x3 = relu(GAT1 out + b1); prep layer2 (h2, al2, self init) ----------
__global__ void k_node2(const float* __restrict__ W1, const float* __restrict__ b1,
                        const float* __restrict__ W2,
                        const float* __restrict__ as2, const float* __restrict__ ad2,
                        int N)
{
    int n = blockIdx.x * blockDim.x + threadIdx.x;
    if (n >= N) return;
    float x3[32];
    #pragma unroll
    for (int h = 0; h < 8; h++) {
        float S   = g_p1[n * 16 + h * 2];
        float den = g_p1[n * 16 + h * 2 + 1];
        float r = S / den;
        #pragma unroll
        for (int c = 0; c < 4; c++)
            x3[h * 4 + c] = fmaxf(fmaf(r, __ldg(&W1[h * 4 + c]), __ldg(&b1[h * 4 + c])), 0.f);
    }
    float h2[16];
    #pragma unroll
    for (int j = 0; j < 16; j++) h2[j] = 0.f;
    #pragma unroll
    for (int i = 0; i < 32; i++) {
        float xi = x3[i];
        #pragma unroll
        for (int j = 0; j < 16; j++) h2[j] = fmaf(xi, __ldg(&W2[i * 16 + j]), h2[j]);
    }
    #pragma unroll
    for (int q = 0; q < 4; q++)
        *(float4*)&g_h2[n * 16 + q * 4] = make_float4(h2[q*4], h2[q*4+1], h2[q*4+2], h2[q*4+3]);
    #pragma unroll
    for (int h = 0; h < 4; h++) {
        float als = 0.f, ald = 0.f;
        #pragma unroll
        for (int c = 0; c < 4; c++) {
            als = fmaf(h2[h * 4 + c], __ldg(&as2[h * 4 + c]), als);
            ald = fmaf(h2[h * 4 + c], __ldg(&ad2[h * 4 + c]), ald);
        }
        g_als2[n * 4 + h] = als;
        g_ald2[n * 4 + h] = ald;
        float ws = __expf(lrelu(als + ald));
        g_den2[n * 4 + h] = ws;
        #pragma unroll
        for (int c = 0; c < 4; c++) g_num2[n * 16 + h * 4 + c] = ws * h2[h * 4 + c];
    }
}

// ---------- G2: layer2 gather, warp per node ----------
__global__ void __launch_bounds__(256) k_gat2(int N)
{
    int warp = (blockIdx.x * blockDim.x + threadIdx.x) >> 5;
    int lane = threadIdx.x & 31;
    if (warp >= N) return;
    int n = warp;
    int start = g_rs[n], end = start + g_cnt[n];
    float4 ad = __ldg((const float4*)&g_ald2[(size_t)n * 4]);
    float num[16], den[4];
    #pragma unroll
    for (int j = 0; j < 16; j++) num[j] = 0.f;
    #pragma unroll
    for (int j = 0; j < 4; j++) den[j] = 0.f;
    for (int i = start + lane; i < end; i += 32) {
        int s = __ldg(&g_adj[i]);
        float4 as = __ldg((const float4*)&g_als2[(size_t)s * 4]);
        float w0 = __expf(lrelu(as.x + ad.x));
        float w1 = __expf(lrelu(as.y + ad.y));
        float w2 = __expf(lrelu(as.z + ad.z));
        float w3 = __expf(lrelu(as.w + ad.w));
        den[0] += w0; den[1] += w1; den[2] += w2; den[3] += w3;
        const float4* hp = (const float4*)&g_h2[(size_t)s * 16];
        float4 h;
        h = __ldg(hp + 0);
        num[0]  = fmaf(w0, h.x, num[0]);  num[1]  = fmaf(w0, h.y, num[1]);
        num[2]  = fmaf(w0, h.z, num[2]);  num[3]  = fmaf(w0, h.w, num[3]);
        h = __ldg(hp + 1);
        num[4]  = fmaf(w1, h.x, num[4]);  num[5]  = fmaf(w1, h.y, num[5]);
        num[6]  = fmaf(w1, h.z, num[6]);  num[7]  = fmaf(w1, h.w, num[7]);
        h = __ldg(hp + 2);
        num[8]  = fmaf(w2, h.x, num[8]);  num[9]  = fmaf(w2, h.y, num[9]);
        num[10] = fmaf(w2, h.z, num[10]); num[11] = fmaf(w2, h.w, num[11]);
        h = __ldg(hp + 3);
        num[12] = fmaf(w3, h.x, num[12]); num[13] = fmaf(w3, h.y, num[13]);
        num[14] = fmaf(w3, h.z, num[14]); num[15] = fmaf(w3, h.w, num[15]);
    }
    #pragma unroll
    for (int j = 0; j < 16; j++) num[j] = wred(num[j]);
    #pragma unroll
    for (int j = 0; j < 4; j++) den[j] = wred(den[j]);
    if (lane == 0) {
        #pragma unroll
        for (int j = 0; j < 16; j++) g_num2[(size_t)n * 16 + j] += num[j];
        #pragma unroll
        for (int j = 0; j < 4; j++)  g_den2[(size_t)n * 4 + j]  += den[j];
    }
}

// ---------- K4: x4 = relu(GAT2 out + b2); prep layer3 ----------
__global__ void k_node3(const float* __restrict__ b2, const float* __restrict__ W3,
                        const float* __restrict__ as3, const float* __restrict__ ad3,
                        int N)
{
    int n = blockIdx.x * blockDim.x + threadIdx.x;
    if (n >= N) return;
    float x4[16];
    #pragma unroll
    for (int h = 0; h < 4; h++) {
        float inv = 1.f / g_den2[n * 4 + h];
        #pragma unroll
        for (int c = 0; c < 4; c++)
            x4[h * 4 + c] = fmaxf(fmaf(g_num2[n * 16 + h * 4 + c], inv, __ldg(&b2[h * 4 + c])), 0.f);
    }
    float h3[8];
    #pragma unroll
    for (int k = 0; k < 8; k++) h3[k] = 0.f;
    #pragma unroll
    for (int j = 0; j < 16; j++) {
        float xj = x4[j];
        #pragma unroll
        for (int k = 0; k < 8; k++) h3[k] = fmaf(xj, __ldg(&W3[j * 8 + k]), h3[k]);
    }
    *(float4*)&g_h3[n * 8]     = make_float4(h3[0], h3[1], h3[2], h3[3]);
    *(float4*)&g_h3[n * 8 + 4] = make_float4(h3[4], h3[5], h3[6], h3[7]);
    #pragma unroll
    for (int h = 0; h < 2; h++) {
        float als = 0.f, ald = 0.f;
        #pragma unroll
        for (int c = 0; c < 4; c++) {
            als = fmaf(h3[h * 4 + c], __ldg(&as3[h * 4 + c]), als);
            ald = fmaf(h3[h * 4 + c], __ldg(&ad3[h * 4 + c]), ald);
        }
        g_als3[n * 2 + h] = als;
        g_ald3[n * 2 + h] = ald;
        float ws = __expf(lrelu(als + ald));
        g_den3[n * 2 + h] = ws;
        #pragma unroll
        for (int c = 0; c < 4; c++) g_num3[n * 8 + h * 4 + c] = ws * h3[h * 4 + c];
    }
}

// ---------- G3: layer3 gather, warp per node ----------
__global__ void __launch_bounds__(256) k_gat3(int N)
{
    int warp = (blockIdx.x * blockDim.x + threadIdx.x) >> 5;
    int lane = threadIdx.x & 31;
    if (warp >= N) return;
    int n = warp;
    int start = g_rs[n], end = start + g_cnt[n];
    float2 ad = __ldg((const float2*)&g_als3[0] + 0);  // placeholder avoided below
    ad = __ldg((const float2*)&g_ald3[(size_t)n * 2]);
    float num[8], den[2];
    #pragma unroll
    for (int j = 0; j < 8; j++) num[j] = 0.f;
    den[0] = 0.f; den[1] = 0.f;
    for (int i = start + lane; i < end; i += 32) {
        int s = __ldg(&g_adj[i]);
        float2 as = __ldg((const float2*)&g_als3[(size_t)s * 2]);
        float w0 = __expf(lrelu(as.x + ad.x));
        float w1 = __expf(lrelu(as.y + ad.y));
        den[0] += w0; den[1] += w1;
        float4 lo = __ldg((const float4*)&g_h3[(size_t)s * 8]);
        float4 hi = __ldg((const float4*)&g_h3[(size_t)s * 8 + 4]);
        num[0] = fmaf(w0, lo.x, num[0]); num[1] = fmaf(w0, lo.y, num[1]);
        num[2] = fmaf(w0, lo.z, num[2]); num[3] = fmaf(w0, lo.w, num[3]);
        num[4] = fmaf(w1, hi.x, num[4]); num[5] = fmaf(w1, hi.y, num[5]);
        num[6] = fmaf(w1, hi.z, num[6]); num[7] = fmaf(w1, hi.w, num[7]);
    }
    #pragma unroll
    for (int j = 0; j < 8; j++) num[j] = wred(num[j]);
    den[0] = wred(den[0]); den[1] = wred(den[1]);
    if (lane == 0) {
        #pragma unroll
        for (int j = 0; j < 8; j++) g_num3[(size_t)n * 8 + j] += num[j];
        g_den3[(size_t)n * 2]     += den[0];
        g_den3[(size_t)n * 2 + 1] += den[1];
    }
}

// ---------- K6: x6 = relu(GAT3 out + b3) ----------
__global__ void k_node4(const float* __restrict__ b3, int N)
{
    int n = blockIdx.x * blockDim.x + threadIdx.x;
    if (n >= N) return;
    float x6[8];
    float inv0 = 1.f / g_den3[n * 2];
    float inv1 = 1.f / g_den3[n * 2 + 1];
    #pragma unroll
    for (int k = 0; k < 8; k++) {
        float inv = (k < 4) ? inv0 : inv1;
        x6[k] = fmaxf(fmaf(g_num3[n * 8 + k], inv, __ldg(&b3[k])), 0.f);
    }
    *(float4*)&g_x6[n * 8]     = make_float4(x6[0], x6[1], x6[2], x6[3]);
    *(float4*)&g_x6[n * 8 + 4] = make_float4(x6[4], x6[5], x6[6], x6[7]);
}

// ---------- GF: final scoring gather over OUT-edges, warp per node; writes out ----------
__global__ void __launch_bounds__(256) k_gatF(const float* __restrict__ lin2w,
                                              float* __restrict__ out, int N)
{
    int warp = (blockIdx.x * blockDim.x + threadIdx.x) >> 5;
    int lane = threadIdx.x & 31;
    if (warp >= N) return;
    int n = warp;
    int start = g_rs[N + n], cnt = g_cnt[N + n];
    int end = start + cnt;
    float4 xa = __ldg((const float4*)&g_x6[(size_t)n * 8]);
    float4 xb = __ldg((const float4*)&g_x6[(size_t)n * 8 + 4]);
    float dot = 0.f;
    float r[8];
    #pragma unroll
    for (int j = 0; j < 8; j++) r[j] = 0.f;
    for (int i = start + lane; i < end; i += 32) {
        int d = __ldg(&g_adj[i]);
        float4 b0 = __ldg((const float4*)&g_x6[(size_t)d * 8]);
        float4 b1 = __ldg((const float4*)&g_x6[(size_t)d * 8 + 4]);
        dot = fmaf(xa.x, b0.x, dot); dot = fmaf(xa.y, b0.y, dot);
        dot = fmaf(xa.z, b0.z, dot); dot = fmaf(xa.w, b0.w, dot);
        dot = fmaf(xb.x, b1.x, dot); dot = fmaf(xb.y, b1.y, dot);
        dot = fmaf(xb.z, b1.z, dot); dot = fmaf(xb.w, b1.w, dot);
        r[0] += b0.x; r[1] += b0.y; r[2] += b0.z; r[3] += b0.w;
        r[4] += b1.x; r[5] += b1.y; r[6] += b1.z; r[7] += b1.w;
    }
    dot = wred(dot);
    #pragma unroll
    for (int j = 0; j < 8; j++) r[j] = wred(r[j]);
    if (lane == 0) {
        float inv = 1.f / (1.f + (float)cnt);
        float selfdot = xa.x*xa.x + xa.y*xa.y + xa.z*xa.z + xa.w*xa.w
                      + xb.x*xb.x + xb.y*xb.y + xb.z*xb.z + xb.w*xb.w;
        float local = (dot + selfdot) * inv;
        float xs[8] = {xa.x, xa.y, xa.z, xa.w, xb.x, xb.y, xb.z, xb.w};
        float g = 0.f;
        #pragma unroll
        for (int j = 0; j < 8; j++) g = fmaf(r[j] + xs[j], __ldg(&lin2w[j]), g);
        out[n] = local + g * inv;
    }
}

extern "C" void kernel_launch(void* const* d_in, const int* in_sizes, int n_in,
                              void* d_out, int out_size)
{
    const float* x1 = (const float*)d_in[0];
    const int*   ei = (const int*)d_in[2];
    int wb = (in_sizes[3] == 7) ? 3 : 4;
    const float* lin1w = (const float*)d_in[wb + 0];
    const float* lin1b = (const float*)d_in[wb + 1];
    const float* lin2w = (const float*)d_in[wb + 2];
    const float* W1    = (const float*)d_in[wb + 3];
    const float* as1   = (const float*)d_in[wb + 4];
    const float* ad1   = (const float*)d_in[wb + 5];
    const float* b1    = (const float*)d_in[wb + 6];
    const float* W2    = (const float*)d_in[wb + 7];
    const float* as2   = (const float*)d_in[wb + 8];
    const float* ad2   = (const float*)d_in[wb + 9];
    const float* b2    = (const float*)d_in[wb + 10];
    const float* W3    = (const float*)d_in[wb + 11];
    const float* as3   = (const float*)d_in[wb + 12];
    const float* ad3   = (const float*)d_in[wb + 13];
    const float* b3    = (const float*)d_in[wb + 14];

    int N = in_sizes[0] / 7;
    int E = in_sizes[2] / 2;
    int L = 2 * N;
    int nb = (N + 255) / 256;
    int eb = (E + 255) / 256;
    int wb8 = (N + 7) / 8;              // warp-per-node grids (8 warps/block)
    int sb = (L + 1023) / 1024;         // scan blocks

    k_zero   <<<(L + 255) / 256, 256>>>(L);
    k_node0  <<<nb, 256>>>(x1, lin1w, lin1b, W1, as1, ad1, N);
    k_hist   <<<eb, 256>>>(ei, E, N);
    k_scan1  <<<sb, 1024>>>(L);
    k_scan2  <<<1, 256>>>(sb);
    k_scan3  <<<sb, 1024>>>(L);
    k_scatter<<<eb, 256>>>(ei, E, N);

    k_gat1   <<<wb8, 256>>>(N);
    k_node2  <<<nb, 256>>>(W1, b1, W2, as2, ad2, N);
    k_gat2   <<<wb8, 256>>>(N);
    k_node3  <<<nb, 256>>>(b2, W3, as3, ad3, N);
    k_gat3   <<<wb8, 256>>>(N);
    k_node4  <<<nb, 256>>>(b3, N);
    k_gatF   <<<wb8, 256>>>(lin2w, (float*)d_out, N);
}

// round 4
// speedup vs baseline: 1.0895x; 1.0895x over previous
#include <cuda_runtime.h>

#define NEG_SLOPE 0.2f
#define MAXN 100000
#define MAXE 3200000

// ---- scratch (static __device__ arrays; no allocation anywhere) ----
__device__ __align__(16) float g_h0 [MAXN];
__device__ __align__(16) float g_p1 [MAXN * 16];   // layer1 per (node,head): {S, den}
__device__ __align__(16) float g_h2 [MAXN * 16];
__device__ __align__(16) float g_ald2[MAXN * 4];
__device__ __align__(16) float g_num2[MAXN * 16];
__device__ __align__(16) float g_den2[MAXN * 4];
__device__ __align__(16) float g_h3 [MAXN * 8];
__device__ __align__(16) float g_ald3[MAXN * 2];
__device__ __align__(16) float g_num3[MAXN * 8];
__device__ __align__(16) float g_den3[MAXN * 2];
__device__ __align__(16) float g_xy [MAXN * 16];   // [0..8)=x6, [8]=y6 (=x6.lin2w)
__device__ __align__(16) float g_acc[MAXN * 4];    // {dot_sum, y_sum, deg, pad}
__device__ __align__(16) float g_ka [16];          // layer1 head consts: kas[8], kad[8]

// ---- CSR scratch (in-adjacency only: neighbors s of each dst d) ----
__device__ int g_cnt[MAXN];
__device__ int g_rs [MAXN];
__device__ int g_cur[MAXN];
__device__ int g_adj[MAXE];
__device__ int g_bsum[256];

__device__ __forceinline__ float lrelu(float x) { return x > 0.f ? x : NEG_SLOPE * x; }

__device__ __forceinline__ float wred(float v) {
    #pragma unroll
    for (int o = 16; o > 0; o >>= 1) v += __shfl_xor_sync(0xffffffffu, v, o);
    return v;
}

__device__ __forceinline__ void red4(float* p, float a, float b, float c, float d) {
    asm volatile("red.global.add.v4.f32 [%0], {%1,%2,%3,%4};"
                 :: "l"(p), "f"(a), "f"(b), "f"(c), "f"(d) : "memory");
}

// ---------- zero in-degree counters ----------
__global__ void k_zero(int N) {
    int i = blockIdx.x * blockDim.x + threadIdx.x;
    if (i < N) g_cnt[i] = 0;
}

// ---------- K0: h0 = relu(x1@lin1w^T + b); layer1 self-term init; ka consts ----------
__global__ void k_node0(const float* __restrict__ x1,
                        const float* __restrict__ lin1w, const float* __restrict__ lin1b,
                        const float* __restrict__ W1,
                        const float* __restrict__ as1, const float* __restrict__ ad1,
                        int N)
{
    int n = blockIdx.x * blockDim.x + threadIdx.x;
    if (n >= N) return;
    if (n == 0) {
        #pragma unroll
        for (int h = 0; h < 8; h++) {
            float kas = 0.f, kad = 0.f;
            #pragma unroll
            for (int c = 0; c < 4; c++) {
                float w = W1[h * 4 + c];
                kas = fmaf(w, as1[h * 4 + c], kas);
                kad = fmaf(w, ad1[h * 4 + c], kad);
            }
            g_ka[h] = kas; g_ka[8 + h] = kad;
        }
    }
    float h0 = __ldg(&lin1b[0]);
    #pragma unroll
    for (int i = 0; i < 7; i++) h0 = fmaf(__ldg(&x1[n * 7 + i]), __ldg(&lin1w[i]), h0);
    h0 = fmaxf(h0, 0.f);
    g_h0[n] = h0;
    #pragma unroll
    for (int h = 0; h < 8; h++) {
        float kas = 0.f, kad = 0.f;
        #pragma unroll
        for (int c = 0; c < 4; c++) {
            float w = __ldg(&W1[h * 4 + c]);
            kas = fmaf(w, __ldg(&as1[h * 4 + c]), kas);
            kad = fmaf(w, __ldg(&ad1[h * 4 + c]), kad);
        }
        float ws = __expf(lrelu(h0 * (kas + kad)));
        g_p1[n * 16 + h * 2]     = ws * h0;  // S (self term)
        g_p1[n * 16 + h * 2 + 1] = ws;       // den (self term)
    }
}

// ---------- CSR build (in-adjacency only) ----------
__global__ void k_hist(const int* __restrict__ ei, int E)
{
    int e = blockIdx.x * blockDim.x + threadIdx.x;
    if (e >= E) return;
    int s = __ldg(&ei[e]);
    int d = __ldg(&ei[E + e]);
    if (s == d) return;
    atomicAdd(&g_cnt[d], 1);
}

__global__ void k_scan1(int L)
{
    __shared__ int sh[1024];
    int i = blockIdx.x * 1024 + threadIdx.x;
    int v = (i < L) ? g_cnt[i] : 0;
    sh[threadIdx.x] = v;
    #pragma unroll
    for (int off = 1; off < 1024; off <<= 1) {
        __syncthreads();
        int t = (threadIdx.x >= off) ? sh[threadIdx.x - off] : 0;
        __syncthreads();
        sh[threadIdx.x] += t;
    }
    __syncthreads();
    if (i < L) g_rs[i] = sh[threadIdx.x] - v;
    if (threadIdx.x == 1023) g_bsum[blockIdx.x] = sh[1023];
}

__global__ void k_scan2(int nb)
{
    __shared__ int sh[256];
    int v = (threadIdx.x < nb) ? g_bsum[threadIdx.x] : 0;
    sh[threadIdx.x] = v;
    #pragma unroll
    for (int off = 1; off < 256; off <<= 1) {
        __syncthreads();
        int t = (threadIdx.x >= off) ? sh[threadIdx.x - off] : 0;
        __syncthreads();
        sh[threadIdx.x] += t;
    }
    __syncthreads();
    if (threadIdx.x < nb) g_bsum[threadIdx.x] = sh[threadIdx.x] - v;
}

__global__ void k_scan3(int L)
{
    int i = blockIdx.x * 1024 + threadIdx.x;
    if (i < L) {
        int r = g_rs[i] + g_bsum[blockIdx.x];
        g_rs[i]  = r;
        g_cur[i] = r;
    }
}

__global__ void k_scatter(const int* __restrict__ ei, int E)
{
    int e = blockIdx.x * blockDim.x + threadIdx.x;
    if (e >= E) return;
    int s = __ldg(&ei[e]);
    int d = __ldg(&ei[E + e]);
    if (s == d) return;
    int p = atomicAdd(&g_cur[d], 1);
    g_adj[p] = s;
}

// ---------- G1: layer1 gather (rank-1), warp per node ----------
__global__ void __launch_bounds__(256) k_gat1(int N)
{
    int warp = (blockIdx.x * blockDim.x + threadIdx.x) >> 5;
    int lane = threadIdx.x & 31;
    if (warp >= N) return;
    int n = warp;
    int start = __ldg(&g_rs[n]), end = start + __ldg(&g_cnt[n]);
    float h0d = __ldg(&g_h0[n]);
    float kas[8], kad[8];
    #pragma unroll
    for (int h = 0; h < 8; h++) { kas[h] = g_ka[h]; kad[h] = g_ka[8 + h] * h0d; }
    float S[8], Wv[8];
    #pragma unroll
    for (int h = 0; h < 8; h++) { S[h] = 0.f; Wv[h] = 0.f; }
    for (int i = start + lane; i < end; i += 32) {
        int s = __ldg(&g_adj[i]);
        float h0s = __ldg(&g_h0[s]);
        #pragma unroll
        for (int h = 0; h < 8; h++) {
            float w = __expf(lrelu(fmaf(kas[h], h0s, kad[h])));
            S[h] = fmaf(w, h0s, S[h]);
            Wv[h] += w;
        }
    }
    #pragma unroll
    for (int h = 0; h < 8; h++) { S[h] = wred(S[h]); Wv[h] = wred(Wv[h]); }
    if (lane == 0) {
        #pragma unroll
        for (int h = 0; h < 8; h++) {
            g_p1[n * 16 + h * 2]     += S[h];
            g_p1[n * 16 + h * 2 + 1] += Wv[h];
        }
    }
}

// ---------- K2: x3 = relu(GAT1 out + b1); prep layer2 ----------
__global__ void k_node2(const float* __restrict__ W1, const float* __restrict__ b1,
                        const float* __restrict__ W2,
                        const float* __restrict__ as2, const float* __restrict__ ad2,
                        int N)
{
    int n = blockIdx.x * blockDim.x + threadIdx.x;
    if (n >= N) return;
    float x3[32];
    #pragma unroll
    for (int h = 0; h < 8; h++) {
        float S   = g_p1[n * 16 + h * 2];
        float den = g_p1[n * 16 + h * 2 + 1];
        float r = S / den;
        #pragma unroll
        for (int c = 0; c < 4; c++)
            x3[h * 4 + c] = fmaxf(fmaf(r, __ldg(&W1[h * 4 + c]), __ldg(&b1[h * 4 + c])), 0.f);
    }
    float h2[16];
    #pragma unroll
    for (int j = 0; j < 16; j++) h2[j] = 0.f;
    #pragma unroll
    for (int i = 0; i < 32; i++) {
        float xi = x3[i];
        #pragma unroll
        for (int j = 0; j < 16; j++) h2[j] = fmaf(xi, __ldg(&W2[i * 16 + j]), h2[j]);
    }
    #pragma unroll
    for (int q = 0; q < 4; q++)
        *(float4*)&g_h2[n * 16 + q * 4] = make_float4(h2[q*4], h2[q*4+1], h2[q*4+2], h2[q*4+3]);
    #pragma unroll
    for (int h = 0; h < 4; h++) {
        float als = 0.f, ald = 0.f;
        #pragma unroll
        for (int c = 0; c < 4; c++) {
            als = fmaf(h2[h * 4 + c], __ldg(&as2[h * 4 + c]), als);
            ald = fmaf(h2[h * 4 + c], __ldg(&ad2[h * 4 + c]), ald);
        }
        g_ald2[n * 4 + h] = ald;
        float ws = __expf(lrelu(als + ald));
        g_den2[n * 4 + h] = ws;
        #pragma unroll
        for (int c = 0; c < 4; c++) g_num2[n * 16 + h * 4 + c] = ws * h2[h * 4 + c];
    }
}

// ---------- G2: layer2 gather, warp per node; als2 recomputed from h2[s] ----------
__global__ void __launch_bounds__(256) k_gat2(const float* __restrict__ as2, int N)
{
    int warp = (blockIdx.x * blockDim.x + threadIdx.x) >> 5;
    int lane = threadIdx.x & 31;
    if (warp >= N) return;
    int n = warp;
    int start = __ldg(&g_rs[n]), end = start + __ldg(&g_cnt[n]);
    float4 ad = *(const float4*)&g_ald2[(size_t)n * 4];
    float a2[16];
    #pragma unroll
    for (int j = 0; j < 16; j++) a2[j] = __ldg(&as2[j]);
    float num[16], den[4];
    #pragma unroll
    for (int j = 0; j < 16; j++) num[j] = 0.f;
    #pragma unroll
    for (int j = 0; j < 4; j++) den[j] = 0.f;
    for (int i = start + lane; i < end; i += 32) {
        int s = __ldg(&g_adj[i]);
        const float4* hp = (const float4*)&g_h2[(size_t)s * 16];
        float4 h0v = __ldg(hp + 0);
        float4 h1v = __ldg(hp + 1);
        float4 h2v = __ldg(hp + 2);
        float4 h3v = __ldg(hp + 3);
        float as0 = h0v.x*a2[0]  + h0v.y*a2[1]  + h0v.z*a2[2]  + h0v.w*a2[3];
        float as1 = h1v.x*a2[4]  + h1v.y*a2[5]  + h1v.z*a2[6]  + h1v.w*a2[7];
        float as2v= h2v.x*a2[8]  + h2v.y*a2[9]  + h2v.z*a2[10] + h2v.w*a2[11];
        float as3 = h3v.x*a2[12] + h3v.y*a2[13] + h3v.z*a2[14] + h3v.w*a2[15];
        float w0 = __expf(lrelu(as0 + ad.x));
        float w1 = __expf(lrelu(as1 + ad.y));
        float w2 = __expf(lrelu(as2v + ad.z));
        float w3 = __expf(lrelu(as3 + ad.w));
        den[0] += w0; den[1] += w1; den[2] += w2; den[3] += w3;
        num[0]  = fmaf(w0, h0v.x, num[0]);  num[1]  = fmaf(w0, h0v.y, num[1]);
        num[2]  = fmaf(w0, h0v.z, num[2]);  num[3]  = fmaf(w0, h0v.w, num[3]);
        num[4]  = fmaf(w1, h1v.x, num[4]);  num[5]  = fmaf(w1, h1v.y, num[5]);
        num[6]  = fmaf(w1, h1v.z, num[6]);  num[7]  = fmaf(w1, h1v.w, num[7]);
        num[8]  = fmaf(w2, h2v.x, num[8]);  num[9]  = fmaf(w2, h2v.y, num[9]);
        num[10] = fmaf(w2, h2v.z, num[10]); num[11] = fmaf(w2, h2v.w, num[11]);
        num[12] = fmaf(w3, h3v.x, num[12]); num[13] = fmaf(w3, h3v.y, num[13]);
        num[14] = fmaf(w3, h3v.z, num[14]); num[15] = fmaf(w3, h3v.w, num[15]);
    }
    #pragma unroll
    for (int j = 0; j < 16; j++) num[j] = wred(num[j]);
    #pragma unroll
    for (int j = 0; j < 4; j++) den[j] = wred(den[j]);
    if (lane == 0) {
        #pragma unroll
        for (int j = 0; j < 16; j++) g_num2[(size_t)n * 16 + j] += num[j];
        #pragma unroll
        for (int j = 0; j < 4; j++)  g_den2[(size_t)n * 4 + j]  += den[j];
    }
}

// ---------- K4: x4 = relu(GAT2 out + b2); prep layer3 ----------
__global__ void k_node3(const float* __restrict__ b2, const float* __restrict__ W3,
                        const float* __restrict__ as3, const float* __restrict__ ad3,
                        int N)
{
    int n = blockIdx.x * blockDim.x + threadIdx.x;
    if (n >= N) return;
    float x4[16];
    #pragma unroll
    for (int h = 0; h < 4; h++) {
        float inv = 1.f / g_den2[n * 4 + h];
        #pragma unroll
        for (int c = 0; c < 4; c++)
            x4[h * 4 + c] = fmaxf(fmaf(g_num2[n * 16 + h * 4 + c], inv, __ldg(&b2[h * 4 + c])), 0.f);
    }
    float h3[8];
    #pragma unroll
    for (int k = 0; k < 8; k++) h3[k] = 0.f;
    #pragma unroll
    for (int j = 0; j < 16; j++) {
        float xj = x4[j];
        #pragma unroll
        for (int k = 0; k < 8; k++) h3[k] = fmaf(xj, __ldg(&W3[j * 8 + k]), h3[k]);
    }
    *(float4*)&g_h3[n * 8]     = make_float4(h3[0], h3[1], h3[2], h3[3]);
    *(float4*)&g_h3[n * 8 + 4] = make_float4(h3[4], h3[5], h3[6], h3[7]);
    #pragma unroll
    for (int h = 0; h < 2; h++) {
        float als = 0.f, ald = 0.f;
        #pragma unroll
        for (int c = 0; c < 4; c++) {
            als = fmaf(h3[h * 4 + c], __ldg(&as3[h * 4 + c]), als);
            ald = fmaf(h3[h * 4 + c], __ldg(&ad3[h * 4 + c]), ald);
        }
        g_ald3[n * 2 + h] = ald;
        float ws = __expf(lrelu(als + ald));
        g_den3[n * 2 + h] = ws;
        #pragma unroll
        for (int c = 0; c < 4; c++) g_num3[n * 8 + h * 4 + c] = ws * h3[h * 4 + c];
    }
}

// ---------- G3: layer3 gather, warp per node; als3 recomputed from h3[s] ----------
__global__ void __launch_bounds__(256) k_gat3(const float* __restrict__ as3, int N)
{
    int warp = (blockIdx.x * blockDim.x + threadIdx.x) >> 5;
    int lane = threadIdx.x & 31;
    if (warp >= N) return;
    int n = warp;
    int start = __ldg(&g_rs[n]), end = start + __ldg(&g_cnt[n]);
    float2 ad = *(const float2*)&g_ald3[(size_t)n * 2];
    float a3[8];
    #pragma unroll
    for (int j = 0; j < 8; j++) a3[j] = __ldg(&as3[j]);
    float num[8], den[2];
    #pragma unroll
    for (int j = 0; j < 8; j++) num[j] = 0.f;
    den[0] = 0.f; den[1] = 0.f;
    for (int i = start + lane; i < end; i += 32) {
        int s = __ldg(&g_adj[i]);
        float4 lo = __ldg((const float4*)&g_h3[(size_t)s * 8]);
        float4 hi = __ldg((const float4*)&g_h3[(size_t)s * 8 + 4]);
        float as0 = lo.x*a3[0] + lo.y*a3[1] + lo.z*a3[2] + lo.w*a3[3];
        float as1 = hi.x*a3[4] + hi.y*a3[5] + hi.z*a3[6] + hi.w*a3[7];
        float w0 = __expf(lrelu(as0 + ad.x));
        float w1 = __expf(lrelu(as1 + ad.y));
        den[0] += w0; den[1] += w1;
        num[0] = fmaf(w0, lo.x, num[0]); num[1] = fmaf(w0, lo.y, num[1]);
        num[2] = fmaf(w0, lo.z, num[2]); num[3] = fmaf(w0, lo.w, num[3]);
        num[4] = fmaf(w1, hi.x, num[4]); num[5] = fmaf(w1, hi.y, num[5]);
        num[6] = fmaf(w1, hi.z, num[6]); num[7] = fmaf(w1, hi.w, num[7]);
    }
    #pragma unroll
    for (int j = 0; j < 8; j++) num[j] = wred(num[j]);
    den[0] = wred(den[0]); den[1] = wred(den[1]);
    if (lane == 0) {
        #pragma unroll
        for (int j = 0; j < 8; j++) g_num3[(size_t)n * 8 + j] += num[j];
        g_den3[(size_t)n * 2]     += den[0];
        g_den3[(size_t)n * 2 + 1] += den[1];
    }
}

// ---------- K6: x6 = relu(GAT3 out + b3); pack {x6, y6}; init g_acc with self terms ----------
__global__ void k_node4(const float* __restrict__ b3, const float* __restrict__ lin2w, int N)
{
    int n = blockIdx.x * blockDim.x + threadIdx.x;
    if (n >= N) return;
    float x6[8];
    float inv0 = 1.f / g_den3[n * 2];
    float inv1 = 1.f / g_den3[n * 2 + 1];
    #pragma unroll
    for (int k = 0; k < 8; k++) {
        float inv = (k < 4) ? inv0 : inv1;
        x6[k] = fmaxf(fmaf(g_num3[n * 8 + k], inv, __ldg(&b3[k])), 0.f);
    }
    float y6 = 0.f, selfdot = 0.f;
    #pragma unroll
    for (int k = 0; k < 8; k++) {
        y6 = fmaf(x6[k], __ldg(&lin2w[k]), y6);
        selfdot = fmaf(x6[k], x6[k], selfdot);
    }
    *(float4*)&g_xy[(size_t)n * 16]     = make_float4(x6[0], x6[1], x6[2], x6[3]);
    *(float4*)&g_xy[(size_t)n * 16 + 4] = make_float4(x6[4], x6[5], x6[6], x6[7]);
    *(float4*)&g_xy[(size_t)n * 16 + 8] = make_float4(y6, 0.f, 0.f, 0.f);
    *(float4*)&g_acc[(size_t)n * 4]     = make_float4(selfdot, y6, 1.f, 0.f);
}

// ---------- EF: final scoring scatter by src: ONE red4 per edge ----------
__global__ void k_edgeF(const int* __restrict__ ei, int E)
{
    int e = blockIdx.x * blockDim.x + threadIdx.x;
    if (e >= E) return;
    int s = __ldg(&ei[e]);
    int d = __ldg(&ei[E + e]);
    if (s == d) return;
    float4 a0 = __ldg((const float4*)&g_xy[(size_t)s * 16]);
    float4 a1 = __ldg((const float4*)&g_xy[(size_t)s * 16 + 4]);
    float4 b0 = __ldg((const float4*)&g_xy[(size_t)d * 16]);
    float4 b1 = __ldg((const float4*)&g_xy[(size_t)d * 16 + 4]);
    float yd  = __ldg(&g_xy[(size_t)d * 16 + 8]);
    float dot = a0.x * b0.x + a0.y * b0.y + a0.z * b0.z + a0.w * b0.w
              + a1.x * b1.x + a1.y * b1.y + a1.z * b1.z + a1.w * b1.w;
    red4(g_acc + (size_t)s * 4, dot, yd, 1.f, 0.f);
}

// ---------- K8: out = (acc_dot + acc_y) / deg ----------
__global__ void k_out(float* __restrict__ out, int N)
{
    int n = blockIdx.x * blockDim.x + threadIdx.x;
    if (n >= N) return;
    float4 a = *(const float4*)&g_acc[(size_t)n * 4];
    out[n] = (a.x + a.y) / a.z;
}

extern "C" void kernel_launch(void* const* d_in, const int* in_sizes, int n_in,
                              void* d_out, int out_size)
{
    const float* x1 = (const float*)d_in[0];
    const int*   ei = (const int*)d_in[2];
    int wb = (in_sizes[3] == 7) ? 3 : 4;
    const float* lin1w = (const float*)d_in[wb + 0];
    const float* lin1b = (const float*)d_in[wb + 1];
    const float* lin2w = (const float*)d_in[wb + 2];
    const float* W1    = (const float*)d_in[wb + 3];
    const float* as1   = (const float*)d_in[wb + 4];
    const float* ad1   = (const float*)d_in[wb + 5];
    const float* b1    = (const float*)d_in[wb + 6];
    const float* W2    = (const float*)d_in[wb + 7];
    const float* as2   = (const float*)d_in[wb + 8];
    const float* ad2   = (const float*)d_in[wb + 9];
    const float* b2    = (const float*)d_in[wb + 10];
    const float* W3    = (const float*)d_in[wb + 11];
    const float* as3   = (const float*)d_in[wb + 12];
    const float* ad3   = (const float*)d_in[wb + 13];
    const float* b3    = (const float*)d_in[wb + 14];

    int N = in_sizes[0] / 7;
    int E = in_sizes[2] / 2;
    int nb = (N + 255) / 256;
    int eb = (E + 255) / 256;
    int wb8 = (N + 7) / 8;              // warp-per-node grids (8 warps/block)
    int sb = (N + 1023) / 1024;         // scan blocks

    k_zero   <<<nb, 256>>>(N);
    k_node0  <<<nb, 256>>>(x1, lin1w, lin1b, W1, as1, ad1, N);
    k_hist   <<<eb, 256>>>(ei, E);
    k_scan1  <<<sb, 1024>>>(N);
    k_scan2  <<<1, 256>>>(sb);
    k_scan3  <<<sb, 1024>>>(N);
    k_scatter<<<eb, 256>>>(ei, E);

    k_gat1   <<<wb8, 256>>>(N);
    k_node2  <<<nb, 256>>>(W1, b1, W2, as2, ad2, N);
    k_gat2   <<<wb8, 256>>>(as2, N);
    k_node3  <<<nb, 256>>>(b2, W3, as3, ad3, N);
    k_gat3   <<<wb8, 256>>>(as3, N);
    k_node4  <<<nb, 256>>>(b3, lin2w, N);
    k_edgeF  <<<eb, 256>>>(ei, E);
    k_out    <<<nb, 256>>>((float*)d_out, N);
}

// round 6
// speedup vs baseline: 1.1809x; 1.0839x over previous
#include <cuda_runtime.h>

#define NEG_SLOPE 0.2f
#define MAXN 100000
#define MAXE 3200000

// ---- scratch (static __device__ arrays; no allocation anywhere) ----
__device__ __align__(16) float g_h0 [MAXN];
__device__ __align__(16) float g_p1 [MAXN * 16];   // layer1 per (node,head): {S, den}
__device__ __align__(16) float g_h2 [MAXN * 16];
__device__ __align__(16) float g_ald2[MAXN * 4];
__device__ __align__(16) float g_num2[MAXN * 16];
__device__ __align__(16) float g_den2[MAXN * 4];
__device__ __align__(16) float g_h3 [MAXN * 8];
__device__ __align__(16) float g_ald3[MAXN * 2];
__device__ __align__(16) float g_num3[MAXN * 8];
__device__ __align__(16) float g_den3[MAXN * 2];
__device__ __align__(16) float g_x6 [MAXN * 8];
__device__ __align__(16) float g_y6 [MAXN];
__device__ __align__(8)  float g_acc[MAXN * 2];    // {dot_sum + y_sum, deg}
__device__ __align__(16) float g_ka [16];          // layer1 head consts: kas[8], kad[8]

// ---- CSR scratch (in-adjacency, self loops INCLUDED; gathers skip s==n) ----
__device__ int g_cnt[MAXN];
__device__ int g_rs [MAXN];
__device__ int g_cur[MAXN];
__device__ int g_adj[MAXE];
__device__ int g_bsum[256];

__device__ __forceinline__ float lrelu(float x) { return x > 0.f ? x : NEG_SLOPE * x; }

__device__ __forceinline__ float wred(float v) {
    #pragma unroll
    for (int o = 16; o > 0; o >>= 1) v += __shfl_xor_sync(0xffffffffu, v, o);
    return v;
}

__device__ __forceinline__ void red2(float* p, float a, float b) {
    asm volatile("red.global.add.v2.f32 [%0], {%1,%2};"
                 :: "l"(p), "f"(a), "f"(b) : "memory");
}

// ---------- K0: h0 = relu(x1@lin1w^T + b); layer1 self init; ka consts; zero cnt ----------
__global__ void k_node0(const float* __restrict__ x1,
                        const float* __restrict__ lin1w, const float* __restrict__ lin1b,
                        const float* __restrict__ W1,
                        const float* __restrict__ as1, const float* __restrict__ ad1,
                        int N)
{
    int n = blockIdx.x * blockDim.x + threadIdx.x;
    if (n >= N) return;
    g_cnt[n] = 0;
    if (n == 0) {
        #pragma unroll
        for (int h = 0; h < 8; h++) {
            float kas = 0.f, kad = 0.f;
            #pragma unroll
            for (int c = 0; c < 4; c++) {
                float w = W1[h * 4 + c];
                kas = fmaf(w, as1[h * 4 + c], kas);
                kad = fmaf(w, ad1[h * 4 + c], kad);
            }
            g_ka[h] = kas; g_ka[8 + h] = kad;
        }
    }
    float h0 = __ldg(&lin1b[0]);
    #pragma unroll
    for (int i = 0; i < 7; i++) h0 = fmaf(__ldg(&x1[n * 7 + i]), __ldg(&lin1w[i]), h0);
    h0 = fmaxf(h0, 0.f);
    g_h0[n] = h0;
    #pragma unroll
    for (int h = 0; h < 8; h++) {
        float kas = 0.f, kad = 0.f;
        #pragma unroll
        for (int c = 0; c < 4; c++) {
            float w = __ldg(&W1[h * 4 + c]);
            kas = fmaf(w, __ldg(&as1[h * 4 + c]), kas);
            kad = fmaf(w, __ldg(&ad1[h * 4 + c]), kad);
        }
        float ws = __expf(lrelu(h0 * (kas + kad)));
        g_p1[n * 16 + h * 2]     = ws * h0;  // S (self term)
        g_p1[n * 16 + h * 2 + 1] = ws;       // den (self term)
    }
}

// ---------- CSR build: count ALL edges by dst (self loops included) ----------
__global__ void k_hist(const int* __restrict__ ei, int E)
{
    int e = blockIdx.x * blockDim.x + threadIdx.x;
    if (e >= E) return;
    atomicAdd(&g_cnt[__ldg(&ei[E + e])], 1);
}

__global__ void k_scan1(int L)
{
    __shared__ int sh[1024];
    int i = blockIdx.x * 1024 + threadIdx.x;
    int v = (i < L) ? g_cnt[i] : 0;
    sh[threadIdx.x] = v;
    #pragma unroll
    for (int off = 1; off < 1024; off <<= 1) {
        __syncthreads();
        int t = (threadIdx.x >= off) ? sh[threadIdx.x - off] : 0;
        __syncthreads();
        sh[threadIdx.x] += t;
    }
    __syncthreads();
    if (i < L) g_rs[i] = sh[threadIdx.x] - v;
    if (threadIdx.x == 1023) g_bsum[blockIdx.x] = sh[1023];
}

__global__ void k_scan2(int nb)
{
    __shared__ int sh[256];
    int v = (threadIdx.x < nb) ? g_bsum[threadIdx.x] : 0;
    sh[threadIdx.x] = v;
    #pragma unroll
    for (int off = 1; off < 256; off <<= 1) {
        __syncthreads();
        int t = (threadIdx.x >= off) ? sh[threadIdx.x - off] : 0;
        __syncthreads();
        sh[threadIdx.x] += t;
    }
    __syncthreads();
    if (threadIdx.x < nb) g_bsum[threadIdx.x] = sh[threadIdx.x] - v;
}

__global__ void k_scan3(int L)
{
    int i = blockIdx.x * 1024 + threadIdx.x;
    if (i < L) {
        int r = g_rs[i] + g_bsum[blockIdx.x];
        g_rs[i]  = r;
        g_cur[i] = r;
    }
}

__global__ void k_scatter(const int* __restrict__ ei, int E)
{
    int e = blockIdx.x * blockDim.x + threadIdx.x;
    if (e >= E) return;
    int s = __ldg(&ei[e]);
    int d = __ldg(&ei[E + e]);
    int p = atomicAdd(&g_cur[d], 1);
    g_adj[p] = s;
}

// ---------- G1: layer1 gather (rank-1), warp per node ----------
__global__ void __launch_bounds__(256) k_gat1(int N)
{
    int warp = (blockIdx.x * blockDim.x + threadIdx.x) >> 5;
    int lane = threadIdx.x & 31;
    if (warp >= N) return;
    int n = warp;
    int start = __ldg(&g_rs[n]), end = start + __ldg(&g_cnt[n]);
    float h0d = __ldg(&g_h0[n]);
    float kas[8], kad[8];
    #pragma unroll
    for (int h = 0; h < 8; h++) { kas[h] = g_ka[h]; kad[h] = g_ka[8 + h] * h0d; }
    float S[8], Wv[8];
    #pragma unroll
    for (int h = 0; h < 8; h++) { S[h] = 0.f; Wv[h] = 0.f; }
    for (int i = start + lane; i < end; i += 32) {
        int s = __ldg(&g_adj[i]);
        if (s == n) continue;                 // skip self loops (re-added in init)
        float h0s = __ldg(&g_h0[s]);
        #pragma unroll
        for (int h = 0; h < 8; h++) {
            float w = __expf(lrelu(fmaf(kas[h], h0s, kad[h])));
            S[h] = fmaf(w, h0s, S[h]);
            Wv[h] += w;
        }
    }
    #pragma unroll
    for (int h = 0; h < 8; h++) { S[h] = wred(S[h]); Wv[h] = wred(Wv[h]); }
    if (lane == 0) {
        #pragma unroll
        for (int h = 0; h < 8; h++) {
            g_p1[n * 16 + h * 2]     += S[h];
            g_p1[n * 16 + h * 2 + 1] += Wv[h];
        }
    }
}

// ---------- K2: x3 = relu(GAT1 out + b1); prep layer2 ----------
__global__ void k_node2(const float* __restrict__ W1, const float* __restrict__ b1,
                        const float* __restrict__ W2,
                        const float* __restrict__ as2, const float* __restrict__ ad2,
                        int N)
{
    int n = blockIdx.x * blockDim.x + threadIdx.x;
    if (n >= N) return;
    float x3[32];
    #pragma unroll
    for (int h = 0; h < 8; h++) {
        float S   = g_p1[n * 16 + h * 2];
        float den = g_p1[n * 16 + h * 2 + 1];
        float r = S / den;
        #pragma unroll
        for (int c = 0; c < 4; c++)
            x3[h * 4 + c] = fmaxf(fmaf(r, __ldg(&W1[h * 4 + c]), __ldg(&b1[h * 4 + c])), 0.f);
    }
    float h2[16];
    #pragma unroll
    for (int j = 0; j < 16; j++) h2[j] = 0.f;
    #pragma unroll
    for (int i = 0; i < 32; i++) {
        float xi = x3[i];
        #pragma unroll
        for (int j = 0; j < 16; j++) h2[j] = fmaf(xi, __ldg(&W2[i * 16 + j]), h2[j]);
    }
    #pragma unroll
    for (int q = 0; q < 4; q++)
        *(float4*)&g_h2[n * 16 + q * 4] = make_float4(h2[q*4], h2[q*4+1], h2[q*4+2], h2[q*4+3]);
    #pragma unroll
    for (int h = 0; h < 4; h++) {
        float als = 0.f, ald = 0.f;
        #pragma unroll
        for (int c = 0; c < 4; c++) {
            als = fmaf(h2[h * 4 + c], __ldg(&as2[h * 4 + c]), als);
            ald = fmaf(h2[h * 4 + c], __ldg(&ad2[h * 4 + c]), ald);
        }
        g_ald2[n * 4 + h] = ald;
        float ws = __expf(lrelu(als + ald));
        g_den2[n * 4 + h] = ws;
        #pragma unroll
        for (int c = 0; c < 4; c++) g_num2[n * 16 + h * 4 + c] = ws * h2[h * 4 + c];
    }
}

// ---------- G2: layer2 gather; als2 recomputed from h2[s] ----------
__global__ void __launch_bounds__(256) k_gat2(const float* __restrict__ as2, int N)
{
    int warp = (blockIdx.x * blockDim.x + threadIdx.x) >> 5;
    int lane = threadIdx.x & 31;
    if (warp >= N) return;
    int n = warp;
    int start = __ldg(&g_rs[n]), end = start + __ldg(&g_cnt[n]);
    float4 ad = *(const float4*)&g_ald2[(size_t)n * 4];
    float a2[16];
    #pragma unroll
    for (int j = 0; j < 16; j++) a2[j] = __ldg(&as2[j]);
    float num[16], den[4];
    #pragma unroll
    for (int j = 0; j < 16; j++) num[j] = 0.f;
    #pragma unroll
    for (int j = 0; j < 4; j++) den[j] = 0.f;
    for (int i = start + lane; i < end; i += 32) {
        int s = __ldg(&g_adj[i]);
        if (s == n) continue;
        const float4* hp = (const float4*)&g_h2[(size_t)s * 16];
        float4 h0v = __ldg(hp + 0);
        float4 h1v = __ldg(hp + 1);
        float4 h2v = __ldg(hp + 2);
        float4 h3v = __ldg(hp + 3);
        float as0 = h0v.x*a2[0]  + h0v.y*a2[1]  + h0v.z*a2[2]  + h0v.w*a2[3];
        float as1 = h1v.x*a2[4]  + h1v.y*a2[5]  + h1v.z*a2[6]  + h1v.w*a2[7];
        float as2v= h2v.x*a2[8]  + h2v.y*a2[9]  + h2v.z*a2[10] + h2v.w*a2[11];
        float as3 = h3v.x*a2[12] + h3v.y*a2[13] + h3v.z*a2[14] + h3v.w*a2[15];
        float w0 = __expf(lrelu(as0 + ad.x));
        float w1 = __expf(lrelu(as1 + ad.y));
        float w2 = __expf(lrelu(as2v + ad.z));
        float w3 = __expf(lrelu(as3 + ad.w));
        den[0] += w0; den[1] += w1; den[2] += w2; den[3] += w3;
        num[0]  = fmaf(w0, h0v.x, num[0]);  num[1]  = fmaf(w0, h0v.y, num[1]);
        num[2]  = fmaf(w0, h0v.z, num[2]);  num[3]  = fmaf(w0, h0v.w, num[3]);
        num[4]  = fmaf(w1, h1v.x, num[4]);  num[5]  = fmaf(w1, h1v.y, num[5]);
        num[6]  = fmaf(w1, h1v.z, num[6]);  num[7]  = fmaf(w1, h1v.w, num[7]);
        num[8]  = fmaf(w2, h2v.x, num[8]);  num[9]  = fmaf(w2, h2v.y, num[9]);
        num[10] = fmaf(w2, h2v.z, num[10]); num[11] = fmaf(w2, h2v.w, num[11]);
        num[12] = fmaf(w3, h3v.x, num[12]); num[13] = fmaf(w3, h3v.y, num[13]);
        num[14] = fmaf(w3, h3v.w == h3v.w ? h3v.z : h3v.z, num[14]); num[15] = fmaf(w3, h3v.w, num[15]);
    }
    #pragma unroll
    for (int j = 0; j < 16; j++) num[j] = wred(num[j]);
    #pragma unroll
    for (int j = 0; j < 4; j++) den[j] = wred(den[j]);
    if (lane == 0) {
        #pragma unroll
        for (int j = 0; j < 16; j++) g_num2[(size_t)n * 16 + j] += num[j];
        #pragma unroll
        for (int j = 0; j < 4; j++)  g_den2[(size_t)n * 4 + j]  += den[j];
    }
}

// ---------- K4: x4 = relu(GAT2 out + b2); prep layer3 ----------
__global__ void k_node3(const float* __restrict__ b2, const float* __restrict__ W3,
                        const float* __restrict__ as3, const float* __restrict__ ad3,
                        int N)
{
    int n = blockIdx.x * blockDim.x + threadIdx.x;
    if (n >= N) return;
    float x4[16];
    #pragma unroll
    for (int h = 0; h < 4; h++) {
        float inv = 1.f / g_den2[n * 4 + h];
        #pragma unroll
        for (int c = 0; c < 4; c++)
            x4[h * 4 + c] = fmaxf(fmaf(g_num2[n * 16 + h * 4 + c], inv, __ldg(&b2[h * 4 + c])), 0.f);
    }
    float h3[8];
    #pragma unroll
    for (int k = 0; k < 8; k++) h3[k] = 0.f;
    #pragma unroll
    for (int j = 0; j < 16; j++) {
        float xj = x4[j];
        #pragma unroll
        for (int k = 0; k < 8; k++) h3[k] = fmaf(xj, __ldg(&W3[j * 8 + k]), h3[k]);
    }
    *(float4*)&g_h3[n * 8]     = make_float4(h3[0], h3[1], h3[2], h3[3]);
    *(float4*)&g_h3[n * 8 + 4] = make_float4(h3[4], h3[5], h3[6], h3[7]);
    #pragma unroll
    for (int h = 0; h < 2; h++) {
        float als = 0.f, ald = 0.f;
        #pragma unroll
        for (int c = 0; c < 4; c++) {
            als = fmaf(h3[h * 4 + c], __ldg(&as3[h * 4 + c]), als);
            ald = fmaf(h3[h * 4 + c], __ldg(&ad3[h * 4 + c]), ald);
        }
        g_ald3[n * 2 + h] = ald;
        float ws = __expf(lrelu(als + ald));
        g_den3[n * 2 + h] = ws;
        #pragma unroll
        for (int c = 0; c < 4; c++) g_num3[n * 8 + h * 4 + c] = ws * h3[h * 4 + c];
    }
}

// ---------- G3: layer3 gather; als3 recomputed from h3[s] ----------
__global__ void __launch_bounds__(256) k_gat3(const float* __restrict__ as3, int N)
{
    int warp = (blockIdx.x * blockDim.x + threadIdx.x) >> 5;
    int lane = threadIdx.x & 31;
    if (warp >= N) return;
    int n = warp;
    int start = __ldg(&g_rs[n]), end = start + __ldg(&g_cnt[n]);
    float2 ad = *(const float2*)&g_ald3[(size_t)n * 2];
    float a3[8];
    #pragma unroll
    for (int j = 0; j < 8; j++) a3[j] = __ldg(&as3[j]);
    float num[8], den[2];
    #pragma unroll
    for (int j = 0; j < 8; j++) num[j] = 0.f;
    den[0] = 0.f; den[1] = 0.f;
    for (int i = start + lane; i < end; i += 32) {
        int s = __ldg(&g_adj[i]);
        if (s == n) continue;
        float4 lo = __ldg((const float4*)&g_h3[(size_t)s * 8]);
        float4 hi = __ldg((const float4*)&g_h3[(size_t)s * 8 + 4]);
        float as0 = lo.x*a3[0] + lo.y*a3[1] + lo.z*a3[2] + lo.w*a3[3];
        float as1 = hi.x*a3[4] + hi.y*a3[5] + hi.z*a3[6] + hi.w*a3[7];
        float w0 = __expf(lrelu(as0 + ad.x));
        float w1 = __expf(lrelu(as1 + ad.y));
        den[0] += w0; den[1] += w1;
        num[0] = fmaf(w0, lo.x, num[0]); num[1] = fmaf(w0, lo.y, num[1]);
        num[2] = fmaf(w0, lo.z, num[2]); num[3] = fmaf(w0, lo.w, num[3]);
        num[4] = fmaf(w1, hi.x, num[4]); num[5] = fmaf(w1, hi.y, num[5]);
        num[6] = fmaf(w1, hi.z, num[6]); num[7] = fmaf(w1, hi.w, num[7]);
    }
    #pragma unroll
    for (int j = 0; j < 8; j++) num[j] = wred(num[j]);
    den[0] = wred(den[0]); den[1] = wred(den[1]);
    if (lane == 0) {
        #pragma unroll
        for (int j = 0; j < 8; j++) g_num3[(size_t)n * 8 + j] += num[j];
        g_den3[(size_t)n * 2]     += den[0];
        g_den3[(size_t)n * 2 + 1] += den[1];
    }
}

// ---------- K6: x6 = relu(GAT3 out + b3); y6 = x6.lin2w; acc init self terms ----------
__global__ void k_node4(const float* __restrict__ b3, const float* __restrict__ lin2w, int N)
{
    int n = blockIdx.x * blockDim.x + threadIdx.x;
    if (n >= N) return;
    float x6[8];
    float inv0 = 1.f / g_den3[n * 2];
    float inv1 = 1.f / g_den3[n * 2 + 1];
    #pragma unroll
    for (int k = 0; k < 8; k++) {
        float inv = (k < 4) ? inv0 : inv1;
        x6[k] = fmaxf(fmaf(g_num3[n * 8 + k], inv, __ldg(&b3[k])), 0.f);
    }
    float y6 = 0.f, selfdot = 0.f;
    #pragma unroll
    for (int k = 0; k < 8; k++) {
        y6 = fmaf(x6[k], __ldg(&lin2w[k]), y6);
        selfdot = fmaf(x6[k], x6[k], selfdot);
    }
    *(float4*)&g_x6[(size_t)n * 8]     = make_float4(x6[0], x6[1], x6[2], x6[3]);
    *(float4*)&g_x6[(size_t)n * 8 + 4] = make_float4(x6[4], x6[5], x6[6], x6[7]);
    g_y6[n] = y6;
    *(float2*)&g_acc[(size_t)n * 2] = make_float2(selfdot + y6, 1.f);
}

// ---------- GF: final scoring via in-CSR; red2{dot+y6d, 1} to acc[s] ----------
__global__ void __launch_bounds__(256) k_gatF(int N)
{
    int warp = (blockIdx.x * blockDim.x + threadIdx.x) >> 5;
    int lane = threadIdx.x & 31;
    if (warp >= N) return;
    int n = warp;                          // n is the DST node; entries are sources s
    int start = __ldg(&g_rs[n]), end = start + __ldg(&g_cnt[n]);
    float4 d0 = *(const float4*)&g_x6[(size_t)n * 8];
    float4 d1 = *(const float4*)&g_x6[(size_t)n * 8 + 4];
    float y6d = g_y6[n];
    for (int i = start + lane; i < end; i += 32) {
        int s = __ldg(&g_adj[i]);
        if (s == n) continue;
        float4 a0 = __ldg((const float4*)&g_x6[(size_t)s * 8]);
        float4 a1 = __ldg((const float4*)&g_x6[(size_t)s * 8 + 4]);
        float dot = a0.x * d0.x + a0.y * d0.y + a0.z * d0.z + a0.w * d0.w
                  + a1.x * d1.x + a1.y * d1.y + a1.z * d1.z + a1.w * d1.w;
        red2(g_acc + (size_t)s * 2, dot + y6d, 1.f);
    }
}

// ---------- K8: out = acc.x / acc.y ----------
__global__ void k_out(float* __restrict__ out, int N)
{
    int n = blockIdx.x * blockDim.x + threadIdx.x;
    if (n >= N) return;
    float2 a = *(const float2*)&g_acc[(size_t)n * 2];
    out[n] = a.x / a.y;
}

extern "C" void kernel_launch(void* const* d_in, const int* in_sizes, int n_in,
                              void* d_out, int out_size)
{
    const float* x1 = (const float*)d_in[0];
    const int*   ei = (const int*)d_in[2];
    int wb = (in_sizes[3] == 7) ? 3 : 4;
    const float* lin1w = (const float*)d_in[wb + 0];
    const float* lin1b = (const float*)d_in[wb + 1];
    const float* lin2w = (const float*)d_in[wb + 2];
    const float* W1    = (const float*)d_in[wb + 3];
    const float* as1   = (const float*)d_in[wb + 4];
    const float* ad1   = (const float*)d_in[wb + 5];
    const float* b1    = (const float*)d_in[wb + 6];
    const float* W2    = (const float*)d_in[wb + 7];
    const float* as2   = (const float*)d_in[wb + 8];
    const float* ad2   = (const float*)d_in[wb + 9];
    const float* b2    = (const float*)d_in[wb + 10];
    const float* W3    = (const float*)d_in[wb + 11];
    const float* as3   = (const float*)d_in[wb + 12];
    const float* ad3   = (const float*)d_in[wb + 13];
    const float* b3    = (const float*)d_in[wb + 14];

    int N = in_sizes[0] / 7;
    int E = in_sizes[2] / 2;
    int nb = (N + 255) / 256;
    int eb = (E + 255) / 256;
    int wb8 = (N + 7) / 8;              // warp-per-node grids (8 warps/block)
    int sb = (N + 1023) / 1024;         // scan blocks

    k_node0  <<<nb, 256>>>(x1, lin1w, lin1b, W1, as1, ad1, N);
    k_hist   <<<eb, 256>>>(ei, E);
    k_scan1  <<<sb, 1024>>>(N);
    k_scan2  <<<1, 256>>>(sb);
    k_scan3  <<<sb, 1024>>>(N);
    k_scatter<<<eb, 256>>>(ei, E);

    k_gat1   <<<wb8, 256>>>(N);
    k_node2  <<<nb, 256>>>(W1, b1, W2, as2, ad2, N);
    k_gat2   <<<wb8, 256>>>(as2, N);
    k_node3  <<<nb, 256>>>(b2, W3, as3, ad3, N);
    k_gat3   <<<wb8, 256>>>(as3, N);
    k_node4  <<<nb, 256>>>(b3, lin2w, N);
    k_gatF   <<<wb8, 256>>>(N);
    k_out    <<<nb, 256>>>((float*)d_out, N);
}

// round 11
// speedup vs baseline: 1.5701x; 1.3296x over previous
#include <cuda_runtime.h>

#define NEG_SLOPE 0.2f
#define MAXN 100000
#define MAXE 3200000

// ---- scratch (static __device__ arrays; no allocation anywhere) ----
__device__ __align__(16) float g_h0 [MAXN];
__device__ __align__(16) float g_h2 [MAXN * 16];
__device__ __align__(16) float g_ald2[MAXN * 4];
__device__ __align__(16) float g_h3 [MAXN * 8];
__device__ __align__(16) float g_ald3[MAXN * 2];
__device__ __align__(16) float g_x6 [MAXN * 8];
__device__ __align__(16) float g_y6 [MAXN];
__device__ __align__(8)  float g_acc[MAXN * 2];    // {dot_sum + y_sum, deg}

// ---- CSR scratch (in-adjacency, self loops INCLUDED; gathers skip s==n) ----
__device__ int g_cnt[MAXN];
__device__ int g_rs [MAXN];
__device__ int g_cur[MAXN];
__device__ int g_adj[MAXE];
__device__ int g_total;

__device__ __forceinline__ float lrelu(float x) { return x > 0.f ? x : NEG_SLOPE * x; }

// reduce across an aligned 8-lane group (xor offsets < 8 stay in-group)
__device__ __forceinline__ float wred8(float v) {
    v += __shfl_xor_sync(0xffffffffu, v, 4);
    v += __shfl_xor_sync(0xffffffffu, v, 2);
    v += __shfl_xor_sync(0xffffffffu, v, 1);
    return v;
}

__device__ __forceinline__ void red2(float* p, float a, float b) {
    asm volatile("red.global.add.v2.f32 [%0], {%1,%2};"
                 :: "l"(p), "f"(a), "f"(b) : "memory");
}

// ---------- K0: h0 = relu(x1@lin1w^T + b); zero cnt + scan total ----------
__global__ void k_node0(const float* __restrict__ x1,
                        const float* __restrict__ lin1w, const float* __restrict__ lin1b,
                        int N)
{
    int n = blockIdx.x * blockDim.x + threadIdx.x;
    if (n >= N) return;
    if (n == 0) g_total = 0;
    g_cnt[n] = 0;
    float h0 = __ldg(&lin1b[0]);
    #pragma unroll
    for (int i = 0; i < 7; i++) h0 = fmaf(__ldg(&x1[n * 7 + i]), __ldg(&lin1w[i]), h0);
    g_h0[n] = fmaxf(h0, 0.f);
}

// ---------- CSR build: count ALL edges by dst ----------
__global__ void k_hist(const int* __restrict__ ei, int E)
{
    int e = blockIdx.x * blockDim.x + threadIdx.x;
    if (e >= E) return;
    atomicAdd(&g_cnt[__ldg(&ei[E + e])], 1);
}

// ---------- single-kernel scan: block scan + atomic base (placement order free) ----------
__global__ void k_scan(int N)
{
    __shared__ int sh[1024];
    __shared__ int base;
    int i = blockIdx.x * 1024 + threadIdx.x;
    int v = (i < N) ? g_cnt[i] : 0;
    sh[threadIdx.x] = v;
    #pragma unroll
    for (int off = 1; off < 1024; off <<= 1) {
        __syncthreads();
        int t = (threadIdx.x >= off) ? sh[threadIdx.x - off] : 0;
        __syncthreads();
        sh[threadIdx.x] += t;
    }
    __syncthreads();
    if (threadIdx.x == 1023) base = atomicAdd(&g_total, sh[1023]);
    __syncthreads();
    if (i < N) {
        int r = base + sh[threadIdx.x] - v;
        g_rs[i]  = r;
        g_cur[i] = r;
    }
}

__global__ void k_scatter(const int* __restrict__ ei, int E)
{
    int e = blockIdx.x * blockDim.x + threadIdx.x;
    if (e >= E) return;
    int s = __ldg(&ei[e]);
    int d = __ldg(&ei[E + e]);
    int p = atomicAdd(&g_cur[d], 1);
    g_adj[p] = s;
}

// ---------- G1+N2: layer1 gather (rank-1) fused with layer2 node prep ----------
// 8 lanes per node (4 nodes/warp). Leader (sub==0) also adds self term and does dense math.
__global__ void __launch_bounds__(256) k_gat1n2(
    const float* __restrict__ W1, const float* __restrict__ as1,
    const float* __restrict__ ad1, const float* __restrict__ b1,
    const float* __restrict__ W2, const float* __restrict__ ad2, int N)
{
    int gid = blockIdx.x * blockDim.x + threadIdx.x;
    int n = gid >> 3;
    int sub = threadIdx.x & 7;
    if (n >= N) return;
    int start = __ldg(&g_rs[n]), end = start + __ldg(&g_cnt[n]);
    float h0d = __ldg(&g_h0[n]);
    float kas[8], kadh[8];
    #pragma unroll
    for (int h = 0; h < 8; h++) {
        float kasv = 0.f, kadv = 0.f;
        #pragma unroll
        for (int c = 0; c < 4; c++) {
            float w = __ldg(&W1[h * 4 + c]);
            kasv = fmaf(w, __ldg(&as1[h * 4 + c]), kasv);
            kadv = fmaf(w, __ldg(&ad1[h * 4 + c]), kadv);
        }
        kas[h] = kasv; kadh[h] = kadv * h0d;
    }
    float S[8], Wv[8];
    if (sub == 0) {   // self-loop term: same formula with h0s = h0d
        #pragma unroll
        for (int h = 0; h < 8; h++) {
            float w = __expf(lrelu(fmaf(kas[h], h0d, kadh[h])));
            S[h] = w * h0d; Wv[h] = w;
        }
    } else {
        #pragma unroll
        for (int h = 0; h < 8; h++) { S[h] = 0.f; Wv[h] = 0.f; }
    }
    for (int i = start + sub; i < end; i += 8) {
        int s = __ldg(&g_adj[i]);
        if (s == n) continue;
        float h0s = __ldg(&g_h0[s]);
        #pragma unroll
        for (int h = 0; h < 8; h++) {
            float w = __expf(lrelu(fmaf(kas[h], h0s, kadh[h])));
            S[h] = fmaf(w, h0s, S[h]);
            Wv[h] += w;
        }
    }
    #pragma unroll
    for (int h = 0; h < 8; h++) { S[h] = wred8(S[h]); Wv[h] = wred8(Wv[h]); }
    if (sub != 0) return;
    // ---- fused node math: x3 = relu((S/W)*W1 + b1); h2 = x3@W2; ald2 ----
    float x3[32];
    #pragma unroll
    for (int h = 0; h < 8; h++) {
        float r = S[h] / Wv[h];
        #pragma unroll
        for (int c = 0; c < 4; c++)
            x3[h * 4 + c] = fmaxf(fmaf(r, __ldg(&W1[h * 4 + c]), __ldg(&b1[h * 4 + c])), 0.f);
    }
    float h2[16];
    #pragma unroll
    for (int j = 0; j < 16; j++) h2[j] = 0.f;
    #pragma unroll
    for (int i = 0; i < 32; i++) {
        float xi = x3[i];
        #pragma unroll
        for (int j = 0; j < 16; j++) h2[j] = fmaf(xi, __ldg(&W2[i * 16 + j]), h2[j]);
    }
    #pragma unroll
    for (int q = 0; q < 4; q++)
        *(float4*)&g_h2[(size_t)n * 16 + q * 4] =
            make_float4(h2[q*4], h2[q*4+1], h2[q*4+2], h2[q*4+3]);
    float ald[4];
    #pragma unroll
    for (int h = 0; h < 4; h++) {
        float a = 0.f;
        #pragma unroll
        for (int c = 0; c < 4; c++) a = fmaf(h2[h * 4 + c], __ldg(&ad2[h * 4 + c]), a);
        ald[h] = a;
    }
    *(float4*)&g_ald2[(size_t)n * 4] = make_float4(ald[0], ald[1], ald[2], ald[3]);
}

// ---------- G2+N3: layer2 gather fused with layer3 node prep ----------
__global__ void __launch_bounds__(256) k_gat2n3(
    const float* __restrict__ as2, const float* __restrict__ b2,
    const float* __restrict__ W3, const float* __restrict__ ad3, int N)
{
    int gid = blockIdx.x * blockDim.x + threadIdx.x;
    int n = gid >> 3;
    int sub = threadIdx.x & 7;
    if (n >= N) return;
    int start = __ldg(&g_rs[n]), end = start + __ldg(&g_cnt[n]);
    float4 ad = *(const float4*)&g_ald2[(size_t)n * 4];
    float a2[16];
    #pragma unroll
    for (int j = 0; j < 16; j++) a2[j] = __ldg(&as2[j]);
    float num[16], den[4];
    #pragma unroll
    for (int j = 0; j < 16; j++) num[j] = 0.f;
    #pragma unroll
    for (int j = 0; j < 4; j++) den[j] = 0.f;

    auto body = [&](const float4& h0v, const float4& h1v, const float4& h2v, const float4& h3v) {
        float as0 = h0v.x*a2[0]  + h0v.y*a2[1]  + h0v.z*a2[2]  + h0v.w*a2[3];
        float as1 = h1v.x*a2[4]  + h1v.y*a2[5]  + h1v.z*a2[6]  + h1v.w*a2[7];
        float asv2= h2v.x*a2[8]  + h2v.y*a2[9]  + h2v.z*a2[10] + h2v.w*a2[11];
        float as3 = h3v.x*a2[12] + h3v.y*a2[13] + h3v.z*a2[14] + h3v.w*a2[15];
        float w0 = __expf(lrelu(as0 + ad.x));
        float w1 = __expf(lrelu(as1 + ad.y));
        float w2 = __expf(lrelu(asv2 + ad.z));
        float w3 = __expf(lrelu(as3 + ad.w));
        den[0] += w0; den[1] += w1; den[2] += w2; den[3] += w3;
        num[0]  = fmaf(w0, h0v.x, num[0]);  num[1]  = fmaf(w0, h0v.y, num[1]);
        num[2]  = fmaf(w0, h0v.z, num[2]);  num[3]  = fmaf(w0, h0v.w, num[3]);
        num[4]  = fmaf(w1, h1v.x, num[4]);  num[5]  = fmaf(w1, h1v.y, num[5]);
        num[6]  = fmaf(w1, h1v.z, num[6]);  num[7]  = fmaf(w1, h1v.w, num[7]);
        num[8]  = fmaf(w2, h2v.x, num[8]);  num[9]  = fmaf(w2, h2v.y, num[9]);
        num[10] = fmaf(w2, h2v.z, num[10]); num[11] = fmaf(w2, h2v.w, num[11]);
        num[12] = fmaf(w3, h3v.x, num[12]); num[13] = fmaf(w3, h3v.y, num[13]);
        num[14] = fmaf(w3, h3v.z, num[14]); num[15] = fmaf(w3, h3v.w, num[15]);
    };

    if (sub == 0) {   // self term from own h2
        const float4* hp = (const float4*)&g_h2[(size_t)n * 16];
        body(__ldg(hp + 0), __ldg(hp + 1), __ldg(hp + 2), __ldg(hp + 3));
    }
    for (int i = start + sub; i < end; i += 8) {
        int s = __ldg(&g_adj[i]);
        if (s == n) continue;
        const float4* hp = (const float4*)&g_h2[(size_t)s * 16];
        body(__ldg(hp + 0), __ldg(hp + 1), __ldg(hp + 2), __ldg(hp + 3));
    }
    #pragma unroll
    for (int j = 0; j < 16; j++) num[j] = wred8(num[j]);
    #pragma unroll
    for (int j = 0; j < 4; j++) den[j] = wred8(den[j]);
    if (sub != 0) return;
    // ---- fused node math: x4 = relu(num/den + b2); h3 = x4@W3; ald3 ----
    float x4[16];
    #pragma unroll
    for (int h = 0; h < 4; h++) {
        float inv = 1.f / den[h];
        #pragma unroll
        for (int c = 0; c < 4; c++)
            x4[h * 4 + c] = fmaxf(fmaf(num[h * 4 + c], inv, __ldg(&b2[h * 4 + c])), 0.f);
    }
    float h3[8];
    #pragma unroll
    for (int k = 0; k < 8; k++) h3[k] = 0.f;
    #pragma unroll
    for (int j = 0; j < 16; j++) {
        float xj = x4[j];
        #pragma unroll
        for (int k = 0; k < 8; k++) h3[k] = fmaf(xj, __ldg(&W3[j * 8 + k]), h3[k]);
    }
    *(float4*)&g_h3[(size_t)n * 8]     = make_float4(h3[0], h3[1], h3[2], h3[3]);
    *(float4*)&g_h3[(size_t)n * 8 + 4] = make_float4(h3[4], h3[5], h3[6], h3[7]);
    float al0 = 0.f, al1 = 0.f;
    #pragma unroll
    for (int c = 0; c < 4; c++) {
        al0 = fmaf(h3[c],     __ldg(&ad3[c]),     al0);
        al1 = fmaf(h3[4 + c], __ldg(&ad3[4 + c]), al1);
    }
    *(float2*)&g_ald3[(size_t)n * 2] = make_float2(al0, al1);
}

// ---------- G3+N4: layer3 gather fused with x6/y6/acc init ----------
__global__ void __launch_bounds__(256) k_gat3n4(
    const float* __restrict__ as3, const float* __restrict__ b3,
    const float* __restrict__ lin2w, int N)
{
    int gid = blockIdx.x * blockDim.x + threadIdx.x;
    int n = gid >> 3;
    int sub = threadIdx.x & 7;
    if (n >= N) return;
    int start = __ldg(&g_rs[n]), end = start + __ldg(&g_cnt[n]);
    float2 ad = *(const float2*)&g_ald3[(size_t)n * 2];
    float a3[8];
    #pragma unroll
    for (int j = 0; j < 8; j++) a3[j] = __ldg(&as3[j]);
    float num[8], den[2];
    #pragma unroll
    for (int j = 0; j < 8; j++) num[j] = 0.f;
    den[0] = 0.f; den[1] = 0.f;

    auto body = [&](const float4& lo, const float4& hi) {
        float as0 = lo.x*a3[0] + lo.y*a3[1] + lo.z*a3[2] + lo.w*a3[3];
        float as1 = hi.x*a3[4] + hi.y*a3[5] + hi.z*a3[6] + hi.w*a3[7];
        float w0 = __expf(lrelu(as0 + ad.x));
        float w1 = __expf(lrelu(as1 + ad.y));
        den[0] += w0; den[1] += w1;
        num[0] = fmaf(w0, lo.x, num[0]); num[1] = fmaf(w0, lo.y, num[1]);
        num[2] = fmaf(w0, lo.z, num[2]); num[3] = fmaf(w0, lo.w, num[3]);
        num[4] = fmaf(w1, hi.x, num[4]); num[5] = fmaf(w1, hi.y, num[5]);
        num[6] = fmaf(w1, hi.z, num[6]); num[7] = fmaf(w1, hi.w, num[7]);
    };

    if (sub == 0) {
        body(__ldg((const float4*)&g_h3[(size_t)n * 8]),
             __ldg((const float4*)&g_h3[(size_t)n * 8 + 4]));
    }
    for (int i = start + sub; i < end; i += 8) {
        int s = __ldg(&g_adj[i]);
        if (s == n) continue;
        body(__ldg((const float4*)&g_h3[(size_t)s * 8]),
             __ldg((const float4*)&g_h3[(size_t)s * 8 + 4]));
    }
    #pragma unroll
    for (int j = 0; j < 8; j++) num[j] = wred8(num[j]);
    den[0] = wred8(den[0]); den[1] = wred8(den[1]);
    if (sub != 0) return;
    // ---- fused: x6 = relu(num/den + b3); y6; acc self init ----
    float inv0 = 1.f / den[0];
    float inv1 = 1.f / den[1];
    float x6[8];
    #pragma unroll
    for (int k = 0; k < 8; k++) {
        float inv = (k < 4) ? inv0 : inv1;
        x6[k] = fmaxf(fmaf(num[k], inv, __ldg(&b3[k])), 0.f);
    }
    float y6 = 0.f, selfdot = 0.f;
    #pragma unroll
    for (int k = 0; k < 8; k++) {
        y6 = fmaf(x6[k], __ldg(&lin2w[k]), y6);
        selfdot = fmaf(x6[k], x6[k], selfdot);
    }
    *(float4*)&g_x6[(size_t)n * 8]     = make_float4(x6[0], x6[1], x6[2], x6[3]);
    *(float4*)&g_x6[(size_t)n * 8 + 4] = make_float4(x6[4], x6[5], x6[6], x6[7]);
    g_y6[n] = y6;
    *(float2*)&g_acc[(size_t)n * 2] = make_float2(selfdot + y6, 1.f);
}

// ---------- GF: final scoring via in-CSR; red2{dot+y6d, 1} to acc[s] ----------
__global__ void __launch_bounds__(256) k_gatF(int N)
{
    int gid = blockIdx.x * blockDim.x + threadIdx.x;
    int n = gid >> 3;                      // n is the DST node; entries are sources s
    int sub = threadIdx.x & 7;
    if (n >= N) return;
    int start = __ldg(&g_rs[n]), end = start + __ldg(&g_cnt[n]);
    float4 d0 = *(const float4*)&g_x6[(size_t)n * 8];
    float4 d1 = *(const float4*)&g_x6[(size_t)n * 8 + 4];
    float y6d = g_y6[n];
    for (int i = start + sub; i < end; i += 8) {
        int s = __ldg(&g_adj[i]);
        if (s == n) continue;
        float4 a0 = __ldg((const float4*)&g_x6[(size_t)s * 8]);
        float4 a1 = __ldg((const float4*)&g_x6[(size_t)s * 8 + 4]);
        float dot = a0.x * d0.x + a0.y * d0.y + a0.z * d0.z + a0.w * d0.w
                  + a1.x * d1.x + a1.y * d1.y + a1.z * d1.z + a1.w * d1.w;
        red2(g_acc + (size_t)s * 2, dot + y6d, 1.f);
    }
}

// ---------- K8: out = acc.x / acc.y ----------
__global__ void k_out(float* __restrict__ out, int N)
{
    int n = blockIdx.x * blockDim.x + threadIdx.x;
    if (n >= N) return;
    float2 a = *(const float2*)&g_acc[(size_t)n * 2];
    out[n] = a.x / a.y;
}

extern "C" void kernel_launch(void* const* d_in, const int* in_sizes, int n_in,
                              void* d_out, int out_size)
{
    const float* x1 = (const float*)d_in[0];
    const int*   ei = (const int*)d_in[2];
    int wb = (in_sizes[3] == 7) ? 3 : 4;
    const float* lin1w = (const float*)d_in[wb + 0];
    const float* lin1b = (const float*)d_in[wb + 1];
    const float* lin2w = (const float*)d_in[wb + 2];
    const float* W1    = (const float*)d_in[wb + 3];
    const float* as1   = (const float*)d_in[wb + 4];
    const float* ad1   = (const float*)d_in[wb + 5];
    const float* b1    = (const float*)d_in[wb + 6];
    const float* W2    = (const float*)d_in[wb + 7];
    const float* as2   = (const float*)d_in[wb + 8];
    const float* ad2   = (const float*)d_in[wb + 9];
    const float* b2    = (const float*)d_in[wb + 10];
    const float* W3    = (const float*)d_in[wb + 11];
    const float* as3   = (const float*)d_in[wb + 12];
    const float* ad3   = (const float*)d_in[wb + 13];
    const float* b3    = (const float*)d_in[wb + 14];

    int N = in_sizes[0] / 7;
    int E = in_sizes[2] / 2;
    int nb = (N + 255) / 256;
    int eb = (E + 255) / 256;
    int gb = (N * 8 + 255) / 256;       // 8 lanes per node, 4 nodes/warp
    int sb = (N + 1023) / 1024;

    k_node0  <<<nb, 256>>>(x1, lin1w, lin1b, N);
    k_hist   <<<eb, 256>>>(ei, E);
    k_scan   <<<sb, 1024>>>(N);
    k_scatter<<<eb, 256>>>(ei, E);

    k_gat1n2 <<<gb, 256>>>(W1, as1, ad1, b1, W2, ad2, N);
    k_gat2n3 <<<gb, 256>>>(as2, b2, W3, ad3, N);
    k_gat3n4 <<<gb, 256>>>(as3, b3, lin2w, N);
    k_gatF   <<<gb, 256>>>(N);
    k_out    <<<nb, 256>>>((float*)d_out, N);
}